// round 1
// baseline (speedup 1.0000x reference)
#include <cuda_runtime.h>
#include <cuda_bf16.h>
#include <math_constants.h>

// BBOX_XFORM_CLIP = log(1000/16)
#define BBOX_XFORM_CLIP 4.135166556742356f

// img dims may arrive as int32 or float32 depending on harness conversion of
// python ints; disambiguate by plausibility of the int interpretation.
__device__ __forceinline__ float load_dim(const void* p) {
    int iv = *(const int*)p;
    if (iv > 0 && iv < (1 << 20)) return (float)iv;
    return __int_as_float(iv);
}

__global__ void __launch_bounds__(256)
postproc_kernel(const float* __restrict__ logits,       // [N,81]
                const float* __restrict__ regr,         // [N,4]
                const float* __restrict__ prop,         // [N,4]
                const void*  __restrict__ imw_p,
                const void*  __restrict__ imh_p,
                float* __restrict__ boxes_out,          // [N*81,4]
                float* __restrict__ scores_out,         // [N*81]
                int N)
{
    const int warp = (int)((blockIdx.x * (unsigned)blockDim.x + threadIdx.x) >> 5);
    const int lane = threadIdx.x & 31;
    if (warp >= N) return;

    // ---------------- softmax over 81 logits ----------------
    const float* lrow = logits + (size_t)warp * 81;
    float v0 = lrow[lane];
    float v1 = lrow[lane + 32];
    float v2 = (lane < 17) ? lrow[lane + 64] : -CUDART_INF_F;

    float m = fmaxf(fmaxf(v0, v1), v2);
    #pragma unroll
    for (int o = 16; o; o >>= 1)
        m = fmaxf(m, __shfl_xor_sync(0xffffffffu, m, o));

    float e0 = __expf(v0 - m);
    float e1 = __expf(v1 - m);
    float e2 = (lane < 17) ? __expf(v2 - m) : 0.0f;

    float s = e0 + e1 + e2;
    #pragma unroll
    for (int o = 16; o; o >>= 1)
        s += __shfl_xor_sync(0xffffffffu, s, o);
    const float inv = 1.0f / s;

    // ---------------- bbox decode (all lanes redundantly; broadcast loads) ----
    const float4 b  = reinterpret_cast<const float4*>(prop)[warp];
    const float4 rc = reinterpret_cast<const float4*>(regr)[warp];

    const float w  = b.z - b.x + 1.0f;
    const float h  = b.w - b.y + 1.0f;
    const float cx = b.x + 0.5f * w;
    const float cy = b.y + 0.5f * h;

    const float dx = rc.x / 10.0f;
    const float dy = rc.y / 10.0f;
    const float dw = fminf(rc.z / 5.0f, BBOX_XFORM_CLIP);
    const float dh = fminf(rc.w / 5.0f, BBOX_XFORM_CLIP);

    const float pcx = dx * w + cx;
    const float pcy = dy * h + cy;
    const float pw  = __expf(dw) * w;
    const float ph  = __expf(dh) * h;

    float x1 = pcx - 0.5f * pw;
    float y1 = pcy - 0.5f * ph;
    float x2 = pcx + 0.5f * pw - 1.0f;
    float y2 = pcy + 0.5f * ph - 1.0f;

    const float wmax = load_dim(imw_p) - 1.0f;
    const float hmax = load_dim(imh_p) - 1.0f;

    // max(...,0) then clip(0, max) == clamp to [0, max]
    x1 = fminf(fmaxf(x1, 0.0f), wmax);
    y1 = fminf(fmaxf(y1, 0.0f), hmax);
    x2 = fminf(fmaxf(x2, 0.0f), wmax);
    y2 = fminf(fmaxf(y2, 0.0f), hmax);

    const float4 box = make_float4(x1, y1, x2, y2);

    // ---------------- writes ----------------
    float4* bo = reinterpret_cast<float4*>(boxes_out) + (size_t)warp * 81;
    bo[lane]      = box;
    bo[lane + 32] = box;
    if (lane < 17) bo[lane + 64] = box;

    float* so = scores_out + (size_t)warp * 81;
    so[lane]      = e0 * inv;
    so[lane + 32] = e1 * inv;
    if (lane < 17) so[lane + 64] = e2 * inv;
}

extern "C" void kernel_launch(void* const* d_in, const int* in_sizes, int n_in,
                              void* d_out, int out_size) {
    const float* logits = (const float*)d_in[0];
    const float* regr   = (const float*)d_in[1];
    const float* prop   = (const float*)d_in[2];
    const void*  imw    = d_in[3];
    const void*  imh    = d_in[4];

    const int N = in_sizes[0] / 81;          // 262144

    float* boxes  = (float*)d_out;           // N*81*4 floats
    float* scores = boxes + (size_t)N * 81 * 4;

    const int threads = 256;                 // 8 warps = 8 rows per block
    const int blocks  = (N + 7) / 8;
    postproc_kernel<<<blocks, threads>>>(logits, regr, prop, imw, imh,
                                         boxes, scores, N);
}

// round 2
// speedup vs baseline: 1.4846x; 1.4846x over previous
#include <cuda_runtime.h>
#include <cuda_bf16.h>
#include <math_constants.h>

// BBOX_XFORM_CLIP = log(1000/16)
#define BBOX_XFORM_CLIP 4.135166556742356f

#define ROWS_PER_BLOCK 16           // 16 rows * 81 classes
#define THREADS 256                  // 8 warps, 2 rows each

// img dims may arrive as int32 or float32; disambiguate by plausibility.
__device__ __forceinline__ float load_dim(const void* p) {
    int iv = *(const int*)p;
    if (iv > 0 && iv < (1 << 20)) return (float)iv;
    return __int_as_float(iv);
}

__global__ void __launch_bounds__(THREADS)
postproc_kernel(const float* __restrict__ logits,       // [N,81]
                const float* __restrict__ regr,         // [N,4]
                const float* __restrict__ prop,         // [N,4]
                const void*  __restrict__ imw_p,
                const void*  __restrict__ imh_p,
                float* __restrict__ boxes_out,          // [N*81,4]
                float* __restrict__ scores_out,         // [N*81]
                int N)
{
    __shared__ alignas(16) float s_boxes[ROWS_PER_BLOCK * 81 * 4];   // 20736 B
    __shared__ alignas(16) float s_scores[ROWS_PER_BLOCK * 81];      //  5184 B

    const int warp = threadIdx.x >> 5;
    const int lane = threadIdx.x & 31;
    const int r0   = blockIdx.x * ROWS_PER_BLOCK;

    const float wmax = load_dim(imw_p) - 1.0f;
    const float hmax = load_dim(imh_p) - 1.0f;

    #pragma unroll
    for (int i = 0; i < 2; i++) {
        const int lr = warp * 2 + i;        // local row 0..15
        const int n  = r0 + lr;             // global row
        if (n >= N) break;

        // ---------------- softmax over 81 logits ----------------
        const float* lrow = logits + (size_t)n * 81;
        float v0 = lrow[lane];
        float v1 = lrow[lane + 32];
        float v2 = (lane < 17) ? lrow[lane + 64] : -CUDART_INF_F;

        float m = fmaxf(fmaxf(v0, v1), v2);
        #pragma unroll
        for (int o = 16; o; o >>= 1)
            m = fmaxf(m, __shfl_xor_sync(0xffffffffu, m, o));

        float e0 = __expf(v0 - m);
        float e1 = __expf(v1 - m);
        float e2 = (lane < 17) ? __expf(v2 - m) : 0.0f;

        float s = e0 + e1 + e2;
        #pragma unroll
        for (int o = 16; o; o >>= 1)
            s += __shfl_xor_sync(0xffffffffu, s, o);
        const float inv = 1.0f / s;

        // ---------------- bbox decode (all lanes redundantly) ----------------
        const float4 b  = reinterpret_cast<const float4*>(prop)[n];
        const float4 rc = reinterpret_cast<const float4*>(regr)[n];

        const float w  = b.z - b.x + 1.0f;
        const float h  = b.w - b.y + 1.0f;
        const float cx = b.x + 0.5f * w;
        const float cy = b.y + 0.5f * h;

        const float dx = rc.x * 0.1f;
        const float dy = rc.y * 0.1f;
        const float dw = fminf(rc.z * 0.2f, BBOX_XFORM_CLIP);
        const float dh = fminf(rc.w * 0.2f, BBOX_XFORM_CLIP);

        const float pcx = dx * w + cx;
        const float pcy = dy * h + cy;
        const float pw  = __expf(dw) * w;
        const float ph  = __expf(dh) * h;

        float x1 = pcx - 0.5f * pw;
        float y1 = pcy - 0.5f * ph;
        float x2 = pcx + 0.5f * pw - 1.0f;
        float y2 = pcy + 0.5f * ph - 1.0f;

        // max(...,0) then clip(0,max) == clamp to [0,max]
        x1 = fminf(fmaxf(x1, 0.0f), wmax);
        y1 = fminf(fmaxf(y1, 0.0f), hmax);
        x2 = fminf(fmaxf(x2, 0.0f), wmax);
        y2 = fminf(fmaxf(y2, 0.0f), hmax);

        const float4 box = make_float4(x1, y1, x2, y2);

        // ---------------- stage to SMEM ----------------
        float4* sb = reinterpret_cast<float4*>(s_boxes) + lr * 81;
        sb[lane]      = box;
        sb[lane + 32] = box;
        if (lane < 17) sb[lane + 64] = box;

        float* ss = s_scores + lr * 81;
        ss[lane]      = e0 * inv;
        ss[lane + 32] = e1 * inv;
        if (lane < 17) ss[lane + 64] = e2 * inv;
    }

    __syncthreads();

    // ---------------- bulk store SMEM -> GMEM (TMA path) ----------------
    if (threadIdx.x == 0) {
        // order generic-proxy STS before async-proxy bulk read
        asm volatile("fence.proxy.async.shared::cta;" ::: "memory");

        unsigned sb_addr = (unsigned)__cvta_generic_to_shared(s_boxes);
        unsigned ss_addr = (unsigned)__cvta_generic_to_shared(s_scores);

        char* gboxes  = (char*)boxes_out  + (size_t)r0 * 81 * 4 * sizeof(float); // r0*1296
        char* gscores = (char*)scores_out + (size_t)r0 * 81 * sizeof(float);     // r0*324

        asm volatile(
            "cp.async.bulk.global.shared::cta.bulk_group [%0], [%1], %2;"
            :: "l"(gboxes), "r"(sb_addr), "n"(ROWS_PER_BLOCK * 81 * 16) : "memory");
        asm volatile(
            "cp.async.bulk.global.shared::cta.bulk_group [%0], [%1], %2;"
            :: "l"(gscores), "r"(ss_addr), "n"(ROWS_PER_BLOCK * 81 * 4) : "memory");
        asm volatile("cp.async.bulk.commit_group;" ::: "memory");
        // CTA must stay alive until the bulk engine has read SMEM
        asm volatile("cp.async.bulk.wait_group.read 0;" ::: "memory");
    }
}

extern "C" void kernel_launch(void* const* d_in, const int* in_sizes, int n_in,
                              void* d_out, int out_size) {
    const float* logits = (const float*)d_in[0];
    const float* regr   = (const float*)d_in[1];
    const float* prop   = (const float*)d_in[2];
    const void*  imw    = d_in[3];
    const void*  imh    = d_in[4];

    const int N = in_sizes[0] / 81;          // 262144

    float* boxes  = (float*)d_out;           // N*81*4 floats
    float* scores = boxes + (size_t)N * 81 * 4;

    const int blocks = (N + ROWS_PER_BLOCK - 1) / ROWS_PER_BLOCK;  // 16384
    postproc_kernel<<<blocks, THREADS>>>(logits, regr, prop, imw, imh,
                                         boxes, scores, N);
}